// round 13
// baseline (speedup 1.0000x reference)
#include <cuda_runtime.h>
#include <math.h>

#define SEQ   512
#define BATCH 32
#define ROWS  16384        // BATCH*SEQ
#define HID   300
#define HDIM  64
#define NH    8
#define DH    8
#define NL    6
#define FF    1200
#define NC    1000

// ---------------- scratch (static device globals; no allocation) ----------------
__device__ float g_acc [ROWS*HID];
__device__ float g_out [ROWS*HID];
__device__ float g_xa  [ROWS*HID];
__device__ float g_tmp [ROWS*HID];
__device__ float g_qh  [ROWS*HDIM];
__device__ float g_kh  [ROWS*HDIM];
__device__ float g_vh  [ROWS*HDIM];
__device__ float g_attn[ROWS*HDIM];
__device__ float g_ffh [ROWS*FF];
__device__ float g_pe  [SEQ*HID];
__device__ float g_part[8*BATCH*HID];
__device__ float g_sums[BATCH*HID];
__device__ float g_logits[BATCH*NC];

// ---------------- positional encoding table ----------------
__global__ void pe_kernel(float* __restrict__ pe) {
    int s = blockIdx.x;
    for (int c = threadIdx.x; c < HID; c += blockDim.x) {
        double expo = (double)(c & ~1) / (double)HID;
        double ang  = (double)s * exp(-expo * 9.210340371976182736); // ln(10000)
        pe[s*HID + c] = (c & 1) ? (float)cos(ang) : (float)sin(ang);
    }
}

// acc = 2*emb[token] + PE   (x2 = emb+PE; acc = x2 + x1)
__global__ void embed_kernel(const int* __restrict__ tok,
                             const float* __restrict__ emb,
                             const float* __restrict__ pe,
                             float* __restrict__ accb) {
    int row = blockIdx.x;
    int s   = row & (SEQ - 1);
    long long t = tok[row];
    const float* er = emb + t * HID;
    const float* pr = pe + s * HID;
    for (int c = threadIdx.x; c < HID; c += blockDim.x) {
        accb[row*HID + c] = 2.f * er[c] + pr[c];
    }
}

// ================= tf32 tensor-core GEMM, 3-stage cp.async pipeline =================
// Block tile (MT*64) x BN, BK=16, 256 threads = 8 warps (4 over M x 2 over N),
// warp tile (MT*16) x (BN/2).

__device__ __forceinline__ void mma_tf32(float d[4], const unsigned a[4],
                                         const unsigned b[2], const float c[4]) {
    asm volatile(
        "mma.sync.aligned.m16n8k8.row.col.f32.tf32.tf32.f32 "
        "{%0,%1,%2,%3}, {%4,%5,%6,%7}, {%8,%9}, {%10,%11,%12,%13};\n"
        : "=f"(d[0]), "=f"(d[1]), "=f"(d[2]), "=f"(d[3])
        : "r"(a[0]), "r"(a[1]), "r"(a[2]), "r"(a[3]),
          "r"(b[0]), "r"(b[1]),
          "f"(c[0]), "f"(c[1]), "f"(c[2]), "f"(c[3]));
}

__device__ __forceinline__ void cp16(void* smem, const void* gmem) {
    unsigned saddr = (unsigned)__cvta_generic_to_shared(smem);
    asm volatile("cp.async.cg.shared.global [%0], [%1], 16;" :: "r"(saddr), "l"(gmem));
}

#define AS_LD 20    // A tile rows padded to 20 floats (conflict-free frag loads)
#define NSTAGE 3

// MT: m16 tiles per warp (2 -> BM=128, 4 -> BM=256)
// HM: head-major scatter store for QKV outputs (N==64, col = d*8+h)
template<int MT, int BN, bool RELU, bool BIAS, bool RES, bool HM>
__device__ __forceinline__ void gemm_body(const float* __restrict__ A,
                                          const float* __restrict__ B,
                                          const float* __restrict__ bias,
                                          const float* __restrict__ res,
                                          float* __restrict__ C,
                                          int N, int K, int bm, int bn) {
    constexpr int BM = MT * 64;
    constexpr int BS_LD = BN + 8;     // %32 == 8 -> conflict-free
    constexpr int NT = BN / 16;       // n-tiles of 8 per warp
    extern __shared__ float dsm[];
    float (*As)[BM][AS_LD] = (float (*)[BM][AS_LD])dsm;
    float (*Bs)[16][BS_LD] = (float (*)[16][BS_LD])(dsm + NSTAGE * BM * AS_LD);

    const int tid  = threadIdx.x;
    const int lane = tid & 31, warp = tid >> 5;
    const int gid  = lane >> 2, tig = lane & 3;
    const int rowb = (warp & 3) * (MT * 16);   // 4 warps over M
    const int nb   = (warp >> 2) * (BN / 2);   // 2 warps over N

    float acc[MT][NT][4];
#pragma unroll
    for (int mt = 0; mt < MT; mt++)
#pragma unroll
        for (int nt = 0; nt < NT; nt++)
#pragma unroll
            for (int i = 0; i < 4; i++) acc[mt][nt][i] = 0.f;

    const int S = (K + 15) / 16;

    auto issue = [&](int s) {
        int buf = s % NSTAGE;
        int k0 = s * 16;
        // A tile: BM x 16 = BM*4 float4 chunks, MT per thread
#pragma unroll
        for (int j = 0; j < MT; j++) {
            int idx = tid + j * 256;
            int r = idx >> 2, c4 = (idx & 3) * 4;
            float* dst = &As[buf][r][c4];
            if (k0 + c4 < K) cp16(dst, A + (size_t)(bm + r) * K + k0 + c4);
            else *(float4*)dst = make_float4(0.f, 0.f, 0.f, 0.f);
        }
        // B tile: 16 x BN = 4*BN float4 chunks
#pragma unroll
        for (int j = 0; j < BN / 64; j++) {
            int idx = tid + j * 256;
            int r = idx / (BN / 4);
            int c4 = (idx % (BN / 4)) * 4;
            float* dst = &Bs[buf][r][c4];
            int gr = k0 + r, gc = bn + c4;
            if (gr < K && gc < N) cp16(dst, B + (size_t)gr * N + gc);
            else *(float4*)dst = make_float4(0.f, 0.f, 0.f, 0.f);
        }
        asm volatile("cp.async.commit_group;");
    };

    issue(0);
    if (S > 1) issue(1);

    for (int s = 0; s < S; s++) {
        if (s + 1 < S) asm volatile("cp.async.wait_group 1;");
        else           asm volatile("cp.async.wait_group 0;");
        __syncthreads();
        if (s + 2 < S) issue(s + 2);

        const float (*as)[AS_LD] = As[s % NSTAGE];
        const float (*bs)[BS_LD] = Bs[s % NSTAGE];
#pragma unroll
        for (int ks = 0; ks < 2; ks++) {
            const int kk = ks * 8;
            unsigned af[MT][4], bf[NT][2];
#pragma unroll
            for (int mt = 0; mt < MT; mt++) {
                int r0 = rowb + mt * 16 + gid;
                af[mt][0] = __float_as_uint(as[r0    ][kk + tig    ]);
                af[mt][1] = __float_as_uint(as[r0 + 8][kk + tig    ]);
                af[mt][2] = __float_as_uint(as[r0    ][kk + tig + 4]);
                af[mt][3] = __float_as_uint(as[r0 + 8][kk + tig + 4]);
            }
#pragma unroll
            for (int nt = 0; nt < NT; nt++) {
                int c0 = nb + nt * 8 + gid;
                bf[nt][0] = __float_as_uint(bs[kk + tig    ][c0]);
                bf[nt][1] = __float_as_uint(bs[kk + tig + 4][c0]);
            }
#pragma unroll
            for (int mt = 0; mt < MT; mt++)
#pragma unroll
                for (int nt = 0; nt < NT; nt++)
                    mma_tf32(acc[mt][nt], af[mt], bf[nt], acc[mt][nt]);
        }
    }

    // epilogue
#pragma unroll
    for (int mt = 0; mt < MT; mt++) {
        int row0 = bm + rowb + mt * 16 + gid;
#pragma unroll
        for (int nt = 0; nt < NT; nt++) {
            int col = bn + nb + nt * 8 + 2 * tig;
#pragma unroll
            for (int half = 0; half < 2; half++) {
                int row = row0 + half * 8;
                float v0 = acc[mt][nt][half * 2 + 0];
                float v1 = acc[mt][nt][half * 2 + 1];
                if (HM) {
                    C[(((size_t)(col & 7)) * ROWS + row) * 8 + (col >> 3)] = v0;
                    C[(((size_t)((col + 1) & 7)) * ROWS + row) * 8 + ((col + 1) >> 3)] = v1;
                } else {
                    if (col < N) {
                        if (BIAS) v0 += bias[col];
                        if (RES)  v0 += res[(size_t)row * N + col];
                        if (RELU) v0 = fmaxf(v0, 0.f);
                        C[(size_t)row * N + col] = v0;
                    }
                    if (col + 1 < N) {
                        if (BIAS) v1 += bias[col + 1];
                        if (RES)  v1 += res[(size_t)row * N + col + 1];
                        if (RELU) v1 = fmaxf(v1, 0.f);
                        C[(size_t)row * N + col + 1] = v1;
                    }
                }
            }
        }
    }
}

template<int MT, int BN, bool RELU, bool BIAS, bool RES>
__global__ void __launch_bounds__(256, 2) gemm_tc(const float* __restrict__ A,
                                                  const float* __restrict__ B,
                                                  const float* __restrict__ bias,
                                                  const float* __restrict__ res,
                                                  float* __restrict__ C,
                                                  int N, int K) {
    gemm_body<MT, BN, RELU, BIAS, RES, false>(A, B, bias, res, C, N, K,
                                              blockIdx.y * (MT * 64), blockIdx.x * BN);
}

// fused QKV with head-major output: grid (1, M/256, 3)
__global__ void __launch_bounds__(256, 2) qkv_tc(const float* __restrict__ A,
                                                 const float* __restrict__ WQa,
                                                 const float* __restrict__ WKa,
                                                 const float* __restrict__ WVa,
                                                 float* __restrict__ Qh,
                                                 float* __restrict__ Kh,
                                                 float* __restrict__ Vh) {
    const float* B = (blockIdx.z == 0) ? WQa : (blockIdx.z == 1) ? WKa : WVa;
    float* C = (blockIdx.z == 0) ? Qh : (blockIdx.z == 1) ? Kh : Vh;
    gemm_body<4, 64, false, false, false, true>(A, B, nullptr, nullptr, C, HDIM, HID,
                                                blockIdx.y * 256, 0);
}

// smem byte sizes
#define SMEM_SZ(MT, BN) ((NSTAGE*(MT*64)*AS_LD + NSTAGE*16*((BN)+8)) * 4)

__device__ __forceinline__ float ex2(float x) {
    float r;
    asm("ex2.approx.f32 %0, %1;" : "=f"(r) : "f"(x));
    return r;
}

// ---------------- attention: head-major inputs, 4 queries/thread ----------------
// grid (NH, BATCH), 128 threads; thread handles queries tid+{0,128,256,384}
__global__ void __launch_bounds__(128) attn_kernel(const float* __restrict__ Qh,
                                                   const float* __restrict__ Kh,
                                                   const float* __restrict__ Vh,
                                                   const int* __restrict__ tok,
                                                   float* __restrict__ O) {
    const int h = blockIdx.x;
    const int b = blockIdx.y;
    const int base = b * SEQ;
    __shared__ float Ks[SEQ][8];
    __shared__ float Vs[SEQ][8];
    __shared__ float mmul[SEQ];
    const int tid = threadIdx.x;   // 128

    const float4* kp = (const float4*)(Kh + ((size_t)h * ROWS + base) * 8);
    const float4* vp = (const float4*)(Vh + ((size_t)h * ROWS + base) * 8);
    float4* Ks4 = (float4*)Ks;
    float4* Vs4 = (float4*)Vs;
#pragma unroll
    for (int i = 0; i < 8; i++) {
        int idx = tid + i * 128;       // 1024 float4 per tensor
        Ks4[idx] = kp[idx];
        Vs4[idx] = vp[idx];
    }
#pragma unroll
    for (int i = 0; i < 4; i++) {
        int idx = tid + i * 128;
        mmul[idx] = (tok[base + idx] == 0) ? 0.f : 1.f;
    }
    __syncthreads();

    // fold 1/sqrt(300)*log2(e) into q; use ex2.approx
    const float scale = 0.05773502691896258f * 1.4426950408889634f;
    float q[4][8];
#pragma unroll
    for (int j = 0; j < 4; j++) {
        const float* qp = Qh + ((size_t)h * ROWS + base + tid + j * 128) * 8;
        float4 x0 = *(const float4*)qp;
        float4 x1 = *(const float4*)(qp + 4);
        q[j][0]=x0.x*scale; q[j][1]=x0.y*scale; q[j][2]=x0.z*scale; q[j][3]=x0.w*scale;
        q[j][4]=x1.x*scale; q[j][5]=x1.y*scale; q[j][6]=x1.z*scale; q[j][7]=x1.w*scale;
    }

    float ssum[4], o[4][8];
#pragma unroll
    for (int j = 0; j < 4; j++) {
        ssum[j] = 0.f;
#pragma unroll
        for (int d = 0; d < 8; d++) o[j][d] = 0.f;
    }

#pragma unroll 2
    for (int k = 0; k < SEQ; k++) {
        float4 k0 = *(const float4*)&Ks[k][0];
        float4 k1 = *(const float4*)&Ks[k][4];
        float m = mmul[k];
        float4 v0 = *(const float4*)&Vs[k][0];
        float4 v1 = *(const float4*)&Vs[k][4];
#pragma unroll
        for (int j = 0; j < 4; j++) {
            float d = q[j][0]*k0.x + q[j][1]*k0.y + q[j][2]*k0.z + q[j][3]*k0.w
                    + q[j][4]*k1.x + q[j][5]*k1.y + q[j][6]*k1.z + q[j][7]*k1.w;
            float p = ex2(d) * m;
            ssum[j] += p;
            o[j][0] += p * v0.x; o[j][1] += p * v0.y; o[j][2] += p * v0.z; o[j][3] += p * v0.w;
            o[j][4] += p * v1.x; o[j][5] += p * v1.y; o[j][6] += p * v1.z; o[j][7] += p * v1.w;
        }
    }

#pragma unroll
    for (int j = 0; j < 4; j++) {
        float inv = 1.f / ssum[j];
        float* op = O + (size_t)(base + tid + j * 128) * HDIM + h * 8;   // head-major concat
        *(float4*)op       = make_float4(o[j][0]*inv, o[j][1]*inv, o[j][2]*inv, o[j][3]*inv);
        *(float4*)(op + 4) = make_float4(o[j][4]*inv, o[j][5]*inv, o[j][6]*inv, o[j][7]*inv);
    }
}

// ---------------- LayerNorm: warp per row, shuffle reductions ----------------
template<bool ACC>
__global__ void __launch_bounds__(256) ln_kernel(const float* __restrict__ in,
                                                 float* __restrict__ outp,
                                                 const float* __restrict__ g,
                                                 const float* __restrict__ bt,
                                                 float* __restrict__ accb) {
    const int warp = threadIdx.x >> 5, lane = threadIdx.x & 31;
    const int row = blockIdx.x * 8 + warp;
    const float* x = in + (size_t)row * HID;

    float v[10];
    float s = 0.f;
#pragma unroll
    for (int i = 0; i < 10; i++) {
        int c = lane + i * 32;
        v[i] = (c < HID) ? x[c] : 0.f;
        s += v[i];
    }
#pragma unroll
    for (int o = 16; o; o >>= 1) s += __shfl_xor_sync(0xffffffffu, s, o);
    float mu = s / HID;

    float sq = 0.f;
#pragma unroll
    for (int i = 0; i < 10; i++) {
        int c = lane + i * 32;
        if (c < HID) { float d = v[i] - mu; sq += d * d; }
    }
#pragma unroll
    for (int o = 16; o; o >>= 1) sq += __shfl_xor_sync(0xffffffffu, sq, o);
    float inv = rsqrtf(sq / (HID - 1) + 1e-8f);

    float gg = g[0], bb = bt[0];
#pragma unroll
    for (int i = 0; i < 10; i++) {
        int c = lane + i * 32;
        if (c < HID) {
            float y = gg * (v[i] - mu) * inv + bb;
            outp[(size_t)row * HID + c] = y;
            if (ACC) accb[(size_t)row * HID + c] += y;
        }
    }
}

// ---------------- sum over sequence, two-stage (deterministic) ----------------
__global__ void seqsum1(const float* __restrict__ in, float* __restrict__ part) {
    int b = blockIdx.x, ch = blockIdx.y, c = threadIdx.x;
    if (c < HID) {
        float a = 0.f;
        const float* p = in + ((size_t)b * SEQ + ch * 64) * HID + c;
        for (int s = 0; s < 64; s++) a += p[(size_t)s * HID];
        part[((size_t)ch * BATCH + b) * HID + c] = a;
    }
}
__global__ void seqsum2(const float* __restrict__ part, float* __restrict__ sums) {
    int b = blockIdx.x, c = threadIdx.x;
    if (c < HID) {
        float a = 0.f;
#pragma unroll
        for (int ch = 0; ch < 8; ch++) a += part[((size_t)ch * BATCH + b) * HID + c];
        sums[b * HID + c] = a;
    }
}

// ---------------- classifier: (B,HID) @ (HID,NC) ----------------
__global__ void classify_kernel(const float* __restrict__ sums, const float* __restrict__ Vd,
                                float* __restrict__ logits) {
    int b = blockIdx.y;
    int c = blockIdx.x * 256 + threadIdx.x;
    __shared__ float srow[HID];
    for (int i = threadIdx.x; i < HID; i += 256) srow[i] = sums[b * HID + i];
    __syncthreads();
    if (c < NC) {
        float a = 0.f;
        for (int k = 0; k < HID; k++) a += srow[k] * Vd[(size_t)k * NC + c];
        logits[b * NC + c] = a;
    }
}

// ---------------- final LN (ddof=1) + softmax over NC ----------------
__global__ void final_kernel(const float* __restrict__ logits,
                             const float* __restrict__ gf, const float* __restrict__ bf,
                             float* __restrict__ outp) {
    const int b = blockIdx.x;
    const int t = threadIdx.x;   // 256
    __shared__ float buf[NC];
    __shared__ float red[256];
    const float* x = logits + (size_t)b * NC;

    float s = 0.f;
    for (int c = t; c < NC; c += 256) { float v = x[c]; buf[c] = v; s += v; }
    red[t] = s; __syncthreads();
    for (int st = 128; st > 0; st >>= 1) { if (t < st) red[t] += red[t + st]; __syncthreads(); }
    float mu = red[0] / NC;
    __syncthreads();

    float sq = 0.f;
    for (int c = t; c < NC; c += 256) { float d = buf[c] - mu; sq += d * d; }
    red[t] = sq; __syncthreads();
    for (int st = 128; st > 0; st >>= 1) { if (t < st) red[t] += red[t + st]; __syncthreads(); }
    float inv = rsqrtf(red[0] / (NC - 1) + 1e-8f);
    float gg = gf[0], bb = bf[0];
    __syncthreads();

    for (int c = t; c < NC; c += 256) buf[c] = gg * (buf[c] - mu) * inv + bb;
    __syncthreads();

    float mx = -1e30f;
    for (int c = t; c < NC; c += 256) mx = fmaxf(mx, buf[c]);
    red[t] = mx; __syncthreads();
    for (int st = 128; st > 0; st >>= 1) { if (t < st) red[t] = fmaxf(red[t], red[t + st]); __syncthreads(); }
    float rmax = red[0];
    __syncthreads();

    float es = 0.f;
    for (int c = t; c < NC; c += 256) es += __expf(buf[c] - rmax);
    red[t] = es; __syncthreads();
    for (int st = 128; st > 0; st >>= 1) { if (t < st) red[t] += red[t + st]; __syncthreads(); }
    float invs = 1.f / red[0];
    __syncthreads();

    for (int c = t; c < NC; c += 256) outp[(size_t)b * NC + c] = __expf(buf[c] - rmax) * invs;
}

// ---------------- launch ----------------
extern "C" void kernel_launch(void* const* d_in, const int* in_sizes, int n_in,
                              void* d_out, int out_size) {
    const int*   xk  = (const int*)  d_in[0];
    const float* emb = (const float*)d_in[1];
    const float* WQ  = (const float*)d_in[2];
    const float* WK  = (const float*)d_in[3];
    const float* WV  = (const float*)d_in[4];
    const float* WO  = (const float*)d_in[5];
    const float* W1  = (const float*)d_in[6];
    const float* b1  = (const float*)d_in[7];
    const float* W2  = (const float*)d_in[8];
    const float* b2  = (const float*)d_in[9];
    const float* g1  = (const float*)d_in[10];
    const float* be1 = (const float*)d_in[11];
    const float* g2  = (const float*)d_in[12];
    const float* be2 = (const float*)d_in[13];
    const float* Vd  = (const float*)d_in[14];
    const float* gf  = (const float*)d_in[15];
    const float* bf  = (const float*)d_in[16];
    float* outp = (float*)d_out;

    float *acc, *outb, *xa, *tmp, *qh, *kh, *vh, *attn, *ffh, *pe, *part, *sums, *logits;
    cudaGetSymbolAddress((void**)&acc,   g_acc);
    cudaGetSymbolAddress((void**)&outb,  g_out);
    cudaGetSymbolAddress((void**)&xa,    g_xa);
    cudaGetSymbolAddress((void**)&tmp,   g_tmp);
    cudaGetSymbolAddress((void**)&qh,    g_qh);
    cudaGetSymbolAddress((void**)&kh,    g_kh);
    cudaGetSymbolAddress((void**)&vh,    g_vh);
    cudaGetSymbolAddress((void**)&attn,  g_attn);
    cudaGetSymbolAddress((void**)&ffh,   g_ffh);
    cudaGetSymbolAddress((void**)&pe,    g_pe);
    cudaGetSymbolAddress((void**)&part,  g_part);
    cudaGetSymbolAddress((void**)&sums,  g_sums);
    cudaGetSymbolAddress((void**)&logits,g_logits);

    // allow >48KB dynamic smem for the pipelined GEMMs (idempotent, capture-safe)
    static bool attr_done = false;
    if (!attr_done) {
        cudaFuncSetAttribute(qkv_tc, cudaFuncAttributeMaxDynamicSharedMemorySize, SMEM_SZ(4,64));
        cudaFuncSetAttribute(gemm_tc<4,64, false,false,true>, cudaFuncAttributeMaxDynamicSharedMemorySize, SMEM_SZ(4,64));
        cudaFuncSetAttribute(gemm_tc<2,128, true,true,false>, cudaFuncAttributeMaxDynamicSharedMemorySize, SMEM_SZ(2,128));
        cudaFuncSetAttribute(gemm_tc<4,64, false,true,true>,  cudaFuncAttributeMaxDynamicSharedMemorySize, SMEM_SZ(4,64));
        attr_done = true;
    }

    pe_kernel<<<SEQ, 128>>>(pe);
    embed_kernel<<<ROWS, 128>>>(xk, emb, pe, acc);

    const int MB256 = ROWS / 256;   // 64 m-blocks for MT=4 kernels
    const int MB128 = ROWS / 128;   // 128 m-blocks for MT=2 kernels

    for (int l = 0; l < NL; l++) {
        const float* wq = WQ + (size_t)l * HID * HDIM;
        const float* wk = WK + (size_t)l * HID * HDIM;
        const float* wv = WV + (size_t)l * HID * HDIM;
        const float* wo = WO + (size_t)l * HDIM * HID;
        const float* w1 = W1 + (size_t)l * HID * FF;
        const float* w2 = W2 + (size_t)l * FF * HID;
        const float* bb1 = b1 + (size_t)l * FF;
        const float* bb2 = b2 + (size_t)l * HID;

        qkv_tc<<<dim3(1, MB256, 3), 256, SMEM_SZ(4,64)>>>(acc, wq, wk, wv, qh, kh, vh);

        attn_kernel<<<dim3(NH, BATCH), 128>>>(qh, kh, vh, xk, attn);

        dim3 go((HID + 63) / 64, MB256);   // 5 n-blocks over N=300
        gemm_tc<4,64, false,false,true><<<go, 256, SMEM_SZ(4,64)>>>(attn, wo, nullptr, acc, tmp, HID, HDIM);
        ln_kernel<false><<<ROWS/8, 256>>>(tmp, xa, g1 + l, be1 + l, nullptr);

        dim3 gf1((FF + 127) / 128, MB128);
        gemm_tc<2,128, true,true,false><<<gf1, 256, SMEM_SZ(2,128)>>>(xa, w1, bb1, nullptr, ffh, FF, HID);
        gemm_tc<4,64, false,true,true><<<go, 256, SMEM_SZ(4,64)>>>(ffh, w2, bb2, xa, tmp, HID, FF);
        ln_kernel<true><<<ROWS/8, 256>>>(tmp, outb, g2 + l, be2 + l, acc);
    }

    seqsum1<<<dim3(BATCH, 8), 320>>>(outb, part);
    seqsum2<<<BATCH, 320>>>(part, sums);
    classify_kernel<<<dim3((NC + 255) / 256, BATCH), 256>>>(sums, Vd, logits);
    final_kernel<<<BATCH, 256>>>(logits, gf, bf, outp);
}

// round 14
// speedup vs baseline: 1.0939x; 1.0939x over previous
#include <cuda_runtime.h>
#include <math.h>

#define SEQ   512
#define BATCH 32
#define ROWS  16384        // BATCH*SEQ
#define HID   300
#define HDIM  64
#define NH    8
#define DH    8
#define NL    6
#define FF    1200
#define NC    1000

// ---------------- scratch (static device globals; no allocation) ----------------
__device__ float g_acc [ROWS*HID];
__device__ float g_out [ROWS*HID];
__device__ float g_xa  [ROWS*HID];
__device__ float g_tmp [ROWS*HID];
__device__ float g_qh  [ROWS*HDIM];
__device__ float g_kh  [ROWS*HDIM];
__device__ float g_vh  [ROWS*HDIM];
__device__ float g_attn[ROWS*HDIM];
__device__ float g_ffh [ROWS*FF];
__device__ float g_pe  [SEQ*HID];
__device__ float g_po  [2*ROWS*NH*8];   // split-K partial outputs
__device__ float g_ps  [2*ROWS*NH];     // split-K partial sums
__device__ float g_part[8*BATCH*HID];
__device__ float g_sums[BATCH*HID];
__device__ float g_logits[BATCH*NC];

// ---------------- positional encoding table ----------------
__global__ void pe_kernel(float* __restrict__ pe) {
    int s = blockIdx.x;
    for (int c = threadIdx.x; c < HID; c += blockDim.x) {
        double expo = (double)(c & ~1) / (double)HID;
        double ang  = (double)s * exp(-expo * 9.210340371976182736); // ln(10000)
        pe[s*HID + c] = (c & 1) ? (float)cos(ang) : (float)sin(ang);
    }
}

// acc = 2*emb[token] + PE   (x2 = emb+PE; acc = x2 + x1)
__global__ void embed_kernel(const int* __restrict__ tok,
                             const float* __restrict__ emb,
                             const float* __restrict__ pe,
                             float* __restrict__ accb) {
    int row = blockIdx.x;
    int s   = row & (SEQ - 1);
    long long t = tok[row];
    const float* er = emb + t * HID;
    const float* pr = pe + s * HID;
    for (int c = threadIdx.x; c < HID; c += blockDim.x) {
        accb[row*HID + c] = 2.f * er[c] + pr[c];
    }
}

// ================= tf32 tensor-core GEMM, 3-stage cp.async pipeline (R8 config) =================

__device__ __forceinline__ void mma_tf32(float d[4], const unsigned a[4],
                                         const unsigned b[2], const float c[4]) {
    asm volatile(
        "mma.sync.aligned.m16n8k8.row.col.f32.tf32.tf32.f32 "
        "{%0,%1,%2,%3}, {%4,%5,%6,%7}, {%8,%9}, {%10,%11,%12,%13};\n"
        : "=f"(d[0]), "=f"(d[1]), "=f"(d[2]), "=f"(d[3])
        : "r"(a[0]), "r"(a[1]), "r"(a[2]), "r"(a[3]),
          "r"(b[0]), "r"(b[1]),
          "f"(c[0]), "f"(c[1]), "f"(c[2]), "f"(c[3]));
}

__device__ __forceinline__ void cp16(void* smem, const void* gmem) {
    unsigned saddr = (unsigned)__cvta_generic_to_shared(smem);
    asm volatile("cp.async.cg.shared.global [%0], [%1], 16;" :: "r"(saddr), "l"(gmem));
}

#define AS_LD 20    // 128x16 A tile, m-major rows padded to 20 floats
#define NSTAGE 3

// HM: head-major scatter store for QKV outputs (N==64, col = d*8+h)
template<int BN, bool RELU, bool BIAS, bool RES, bool HM>
__device__ __forceinline__ void gemm_body(const float* __restrict__ A,
                                          const float* __restrict__ B,
                                          const float* __restrict__ bias,
                                          const float* __restrict__ res,
                                          float* __restrict__ C,
                                          int N, int K, int bm, int bn) {
    constexpr int BS_LD = BN + 8;     // %32 == 8 -> conflict-free
    constexpr int NT = BN / 16;       // n-tiles of 8 per warp
    extern __shared__ float dsm[];
    float (*As)[128][AS_LD] = (float (*)[128][AS_LD])dsm;
    float (*Bs)[16][BS_LD]  = (float (*)[16][BS_LD])(dsm + NSTAGE * 128 * AS_LD);

    const int tid  = threadIdx.x;
    const int lane = tid & 31, warp = tid >> 5;
    const int gid  = lane >> 2, tig = lane & 3;
    const int rowb = (warp & 3) * 32;          // 4 warps over M
    const int nb   = (warp >> 2) * (BN / 2);   // 2 warps over N

    float acc[2][NT][4];
#pragma unroll
    for (int mt = 0; mt < 2; mt++)
#pragma unroll
        for (int nt = 0; nt < NT; nt++)
#pragma unroll
            for (int i = 0; i < 4; i++) acc[mt][nt][i] = 0.f;

    const int S = (K + 15) / 16;

    auto issue = [&](int s) {
        int buf = s % NSTAGE;
        int k0 = s * 16;
#pragma unroll
        for (int j = 0; j < 2; j++) {
            int idx = tid + j * 256;
            int r = idx >> 2, c4 = (idx & 3) * 4;
            float* dst = &As[buf][r][c4];
            if (k0 + c4 < K) cp16(dst, A + (size_t)(bm + r) * K + k0 + c4);
            else *(float4*)dst = make_float4(0.f, 0.f, 0.f, 0.f);
        }
#pragma unroll
        for (int j = 0; j < BN / 64; j++) {
            int idx = tid + j * 256;
            int r = idx / (BN / 4);
            int c4 = (idx % (BN / 4)) * 4;
            float* dst = &Bs[buf][r][c4];
            int gr = k0 + r, gc = bn + c4;
            if (gr < K && gc < N) cp16(dst, B + (size_t)gr * N + gc);
            else *(float4*)dst = make_float4(0.f, 0.f, 0.f, 0.f);
        }
        asm volatile("cp.async.commit_group;");
    };

    issue(0);
    if (S > 1) issue(1);

    for (int s = 0; s < S; s++) {
        if (s + 1 < S) asm volatile("cp.async.wait_group 1;");
        else           asm volatile("cp.async.wait_group 0;");
        __syncthreads();
        if (s + 2 < S) issue(s + 2);

        const float (*as)[AS_LD] = As[s % NSTAGE];
        const float (*bs)[BS_LD] = Bs[s % NSTAGE];
#pragma unroll
        for (int ks = 0; ks < 2; ks++) {
            const int kk = ks * 8;
            unsigned af[2][4], bf[NT][2];
#pragma unroll
            for (int mt = 0; mt < 2; mt++) {
                int r0 = rowb + mt * 16 + gid;
                af[mt][0] = __float_as_uint(as[r0    ][kk + tig    ]);
                af[mt][1] = __float_as_uint(as[r0 + 8][kk + tig    ]);
                af[mt][2] = __float_as_uint(as[r0    ][kk + tig + 4]);
                af[mt][3] = __float_as_uint(as[r0 + 8][kk + tig + 4]);
            }
#pragma unroll
            for (int nt = 0; nt < NT; nt++) {
                int c0 = nb + nt * 8 + gid;
                bf[nt][0] = __float_as_uint(bs[kk + tig    ][c0]);
                bf[nt][1] = __float_as_uint(bs[kk + tig + 4][c0]);
            }
#pragma unroll
            for (int mt = 0; mt < 2; mt++)
#pragma unroll
                for (int nt = 0; nt < NT; nt++)
                    mma_tf32(acc[mt][nt], af[mt], bf[nt], acc[mt][nt]);
        }
    }

    // epilogue
#pragma unroll
    for (int mt = 0; mt < 2; mt++) {
        int row0 = bm + rowb + mt * 16 + gid;
#pragma unroll
        for (int nt = 0; nt < NT; nt++) {
            int col = bn + nb + nt * 8 + 2 * tig;
#pragma unroll
            for (int half = 0; half < 2; half++) {
                int row = row0 + half * 8;
                float v0 = acc[mt][nt][half * 2 + 0];
                float v1 = acc[mt][nt][half * 2 + 1];
                if (HM) {
                    C[(((size_t)(col & 7)) * ROWS + row) * 8 + (col >> 3)] = v0;
                    C[(((size_t)((col + 1) & 7)) * ROWS + row) * 8 + ((col + 1) >> 3)] = v1;
                } else {
                    if (col < N) {
                        if (BIAS) v0 += bias[col];
                        if (RES)  v0 += res[(size_t)row * N + col];
                        if (RELU) v0 = fmaxf(v0, 0.f);
                        C[(size_t)row * N + col] = v0;
                    }
                    if (col + 1 < N) {
                        if (BIAS) v1 += bias[col + 1];
                        if (RES)  v1 += res[(size_t)row * N + col + 1];
                        if (RELU) v1 = fmaxf(v1, 0.f);
                        C[(size_t)row * N + col + 1] = v1;
                    }
                }
            }
        }
    }
}

template<int BN, bool RELU, bool BIAS, bool RES>
__global__ void __launch_bounds__(256) gemm_tc(const float* __restrict__ A,
                                               const float* __restrict__ B,
                                               const float* __restrict__ bias,
                                               const float* __restrict__ res,
                                               float* __restrict__ C,
                                               int N, int K) {
    gemm_body<BN, RELU, BIAS, RES, false>(A, B, bias, res, C, N, K,
                                          blockIdx.y * 128, blockIdx.x * BN);
}

// fused QKV with head-major output: grid (1, M/128, 3)
__global__ void __launch_bounds__(256) qkv_tc(const float* __restrict__ A,
                                              const float* __restrict__ WQa,
                                              const float* __restrict__ WKa,
                                              const float* __restrict__ WVa,
                                              float* __restrict__ Qh,
                                              float* __restrict__ Kh,
                                              float* __restrict__ Vh) {
    const float* B = (blockIdx.z == 0) ? WQa : (blockIdx.z == 1) ? WKa : WVa;
    float* C = (blockIdx.z == 0) ? Qh : (blockIdx.z == 1) ? Kh : Vh;
    gemm_body<64, false, false, false, true>(A, B, nullptr, nullptr, C, HDIM, HID,
                                             blockIdx.y * 128, 0);
}

// smem byte sizes for the pipeline
#define SMEM_BN64  ((NSTAGE*128*AS_LD + NSTAGE*16*(64+8)) * 4)
#define SMEM_BN128 ((NSTAGE*128*AS_LD + NSTAGE*16*(128+8)) * 4)

__device__ __forceinline__ float ex2(float x) {
    float r;
    asm("ex2.approx.f32 %0, %1;" : "=f"(r) : "f"(x));
    return r;
}

// ---------------- attention part 1: split-K, 4 queries/thread ----------------
// grid (NH, BATCH, 2): z = key-half; 128 threads; thread handles queries tid+{0,128,256,384}
// writes partial (ssum, o[8]) per (query, head, half)
__global__ void __launch_bounds__(128) attn_part(const float* __restrict__ Qh,
                                                 const float* __restrict__ Kh,
                                                 const float* __restrict__ Vh,
                                                 const int* __restrict__ tok,
                                                 float* __restrict__ po,
                                                 float* __restrict__ ps) {
    const int h = blockIdx.x;
    const int b = blockIdx.y;
    const int z = blockIdx.z;              // key half
    const int base = b * SEQ;
    const int koff = z * 256;
    __shared__ float Ks[256][8];
    __shared__ float Vs[256][8];
    __shared__ float mmul[256];
    const int tid = threadIdx.x;   // 128

    const float4* kp = (const float4*)(Kh + ((size_t)h * ROWS + base + koff) * 8);
    const float4* vp = (const float4*)(Vh + ((size_t)h * ROWS + base + koff) * 8);
    float4* Ks4 = (float4*)Ks;
    float4* Vs4 = (float4*)Vs;
#pragma unroll
    for (int i = 0; i < 4; i++) {
        int idx = tid + i * 128;       // 512 float4 per tensor
        Ks4[idx] = kp[idx];
        Vs4[idx] = vp[idx];
    }
#pragma unroll
    for (int i = 0; i < 2; i++) {
        int idx = tid + i * 128;
        mmul[idx] = (tok[base + koff + idx] == 0) ? 0.f : 1.f;
    }
    __syncthreads();

    // fold 1/sqrt(300)*log2(e) into q; use ex2.approx
    const float scale = 0.05773502691896258f * 1.4426950408889634f;
    float q[4][8];
#pragma unroll
    for (int j = 0; j < 4; j++) {
        const float* qp = Qh + ((size_t)h * ROWS + base + tid + j * 128) * 8;
        float4 x0 = *(const float4*)qp;
        float4 x1 = *(const float4*)(qp + 4);
        q[j][0]=x0.x*scale; q[j][1]=x0.y*scale; q[j][2]=x0.z*scale; q[j][3]=x0.w*scale;
        q[j][4]=x1.x*scale; q[j][5]=x1.y*scale; q[j][6]=x1.z*scale; q[j][7]=x1.w*scale;
    }

    float ssum[4], o[4][8];
#pragma unroll
    for (int j = 0; j < 4; j++) {
        ssum[j] = 0.f;
#pragma unroll
        for (int d = 0; d < 8; d++) o[j][d] = 0.f;
    }

#pragma unroll 2
    for (int k = 0; k < 256; k++) {
        float4 k0 = *(const float4*)&Ks[k][0];
        float4 k1 = *(const float4*)&Ks[k][4];
        float m = mmul[k];
        float4 v0 = *(const float4*)&Vs[k][0];
        float4 v1 = *(const float4*)&Vs[k][4];
#pragma unroll
        for (int j = 0; j < 4; j++) {
            float d = q[j][0]*k0.x + q[j][1]*k0.y + q[j][2]*k0.z + q[j][3]*k0.w
                    + q[j][4]*k1.x + q[j][5]*k1.y + q[j][6]*k1.z + q[j][7]*k1.w;
            float p = ex2(d) * m;
            ssum[j] += p;
            o[j][0] += p * v0.x; o[j][1] += p * v0.y; o[j][2] += p * v0.z; o[j][3] += p * v0.w;
            o[j][4] += p * v1.x; o[j][5] += p * v1.y; o[j][6] += p * v1.z; o[j][7] += p * v1.w;
        }
    }

#pragma unroll
    for (int j = 0; j < 4; j++) {
        size_t grow = (size_t)base + tid + j * 128;       // global row
        size_t idx = ((size_t)z * ROWS + grow) * NH + h;  // (half, row, head)
        ps[idx] = ssum[j];
        float* op = po + idx * 8;
        *(float4*)op       = make_float4(o[j][0], o[j][1], o[j][2], o[j][3]);
        *(float4*)(op + 4) = make_float4(o[j][4], o[j][5], o[j][6], o[j][7]);
    }
}

// ---------------- attention part 2: combine halves, normalize ----------------
// one thread per (row, head); t = row*NH + h -> coalesced reads and writes
__global__ void __launch_bounds__(256) attn_combine(const float* __restrict__ po,
                                                    const float* __restrict__ ps,
                                                    float* __restrict__ O) {
    const int t = blockIdx.x * 256 + threadIdx.x;   // ROWS*NH total
    const size_t i0 = (size_t)t;                    // half 0
    const size_t i1 = (size_t)ROWS * NH + t;        // half 1
    float inv = 1.f / (ps[i0] + ps[i1]);
    const float4* p0 = (const float4*)(po + i0 * 8);
    const float4* p1 = (const float4*)(po + i1 * 8);
    float4 a0 = p0[0], a1 = p0[1];
    float4 b0 = p1[0], b1 = p1[1];
    float4 r0 = make_float4((a0.x+b0.x)*inv, (a0.y+b0.y)*inv, (a0.z+b0.z)*inv, (a0.w+b0.w)*inv);
    float4 r1 = make_float4((a1.x+b1.x)*inv, (a1.y+b1.y)*inv, (a1.z+b1.z)*inv, (a1.w+b1.w)*inv);
    // O[row][h*8 + d]; t = row*NH + h  -> O + t*8 is exactly row*64 + h*8
    float4* op = (float4*)(O + (size_t)t * 8);
    op[0] = r0;
    op[1] = r1;
}

// ---------------- LayerNorm: warp per row, shuffle reductions ----------------
template<bool ACC>
__global__ void __launch_bounds__(256) ln_kernel(const float* __restrict__ in,
                                                 float* __restrict__ outp,
                                                 const float* __restrict__ g,
                                                 const float* __restrict__ bt,
                                                 float* __restrict__ accb) {
    const int warp = threadIdx.x >> 5, lane = threadIdx.x & 31;
    const int row = blockIdx.x * 8 + warp;
    const float* x = in + (size_t)row * HID;

    float v[10];
    float s = 0.f;
#pragma unroll
    for (int i = 0; i < 10; i++) {
        int c = lane + i * 32;
        v[i] = (c < HID) ? x[c] : 0.f;
        s += v[i];
    }
#pragma unroll
    for (int o = 16; o; o >>= 1) s += __shfl_xor_sync(0xffffffffu, s, o);
    float mu = s / HID;

    float sq = 0.f;
#pragma unroll
    for (int i = 0; i < 10; i++) {
        int c = lane + i * 32;
        if (c < HID) { float d = v[i] - mu; sq += d * d; }
    }
#pragma unroll
    for (int o = 16; o; o >>= 1) sq += __shfl_xor_sync(0xffffffffu, sq, o);
    float inv = rsqrtf(sq / (HID - 1) + 1e-8f);

    float gg = g[0], bb = bt[0];
#pragma unroll
    for (int i = 0; i < 10; i++) {
        int c = lane + i * 32;
        if (c < HID) {
            float y = gg * (v[i] - mu) * inv + bb;
            outp[(size_t)row * HID + c] = y;
            if (ACC) accb[(size_t)row * HID + c] += y;
        }
    }
}

// ---------------- sum over sequence, two-stage (deterministic) ----------------
__global__ void seqsum1(const float* __restrict__ in, float* __restrict__ part) {
    int b = blockIdx.x, ch = blockIdx.y, c = threadIdx.x;
    if (c < HID) {
        float a = 0.f;
        const float* p = in + ((size_t)b * SEQ + ch * 64) * HID + c;
        for (int s = 0; s < 64; s++) a += p[(size_t)s * HID];
        part[((size_t)ch * BATCH + b) * HID + c] = a;
    }
}
__global__ void seqsum2(const float* __restrict__ part, float* __restrict__ sums) {
    int b = blockIdx.x, c = threadIdx.x;
    if (c < HID) {
        float a = 0.f;
#pragma unroll
        for (int ch = 0; ch < 8; ch++) a += part[((size_t)ch * BATCH + b) * HID + c];
        sums[b * HID + c] = a;
    }
}

// ---------------- classifier: (B,HID) @ (HID,NC) ----------------
__global__ void classify_kernel(const float* __restrict__ sums, const float* __restrict__ Vd,
                                float* __restrict__ logits) {
    int b = blockIdx.y;
    int c = blockIdx.x * 256 + threadIdx.x;
    __shared__ float srow[HID];
    for (int i = threadIdx.x; i < HID; i += 256) srow[i] = sums[b * HID + i];
    __syncthreads();
    if (c < NC) {
        float a = 0.f;
        for (int k = 0; k < HID; k++) a += srow[k] * Vd[(size_t)k * NC + c];
        logits[b * NC + c] = a;
    }
}

// ---------------- final LN (ddof=1) + softmax over NC ----------------
__global__ void final_kernel(const float* __restrict__ logits,
                             const float* __restrict__ gf, const float* __restrict__ bf,
                             float* __restrict__ outp) {
    const int b = blockIdx.x;
    const int t = threadIdx.x;   // 256
    __shared__ float buf[NC];
    __shared__ float red[256];
    const float* x = logits + (size_t)b * NC;

    float s = 0.f;
    for (int c = t; c < NC; c += 256) { float v = x[c]; buf[c] = v; s += v; }
    red[t] = s; __syncthreads();
    for (int st = 128; st > 0; st >>= 1) { if (t < st) red[t] += red[t + st]; __syncthreads(); }
    float mu = red[0] / NC;
    __syncthreads();

    float sq = 0.f;
    for (int c = t; c < NC; c += 256) { float d = buf[c] - mu; sq += d * d; }
    red[t] = sq; __syncthreads();
    for (int st = 128; st > 0; st >>= 1) { if (t < st) red[t] += red[t + st]; __syncthreads(); }
    float inv = rsqrtf(red[0] / (NC - 1) + 1e-8f);
    float gg = gf[0], bb = bf[0];
    __syncthreads();

    for (int c = t; c < NC; c += 256) buf[c] = gg * (buf[c] - mu) * inv + bb;
    __syncthreads();

    float mx = -1e30f;
    for (int c = t; c < NC; c += 256) mx = fmaxf(mx, buf[c]);
    red[t] = mx; __syncthreads();
    for (int st = 128; st > 0; st >>= 1) { if (t < st) red[t] = fmaxf(red[t], red[t + st]); __syncthreads(); }
    float rmax = red[0];
    __syncthreads();

    float es = 0.f;
    for (int c = t; c < NC; c += 256) es += __expf(buf[c] - rmax);
    red[t] = es; __syncthreads();
    for (int st = 128; st > 0; st >>= 1) { if (t < st) red[t] += red[t + st]; __syncthreads(); }
    float invs = 1.f / red[0];
    __syncthreads();

    for (int c = t; c < NC; c += 256) outp[(size_t)b * NC + c] = __expf(buf[c] - rmax) * invs;
}

// ---------------- launch ----------------
extern "C" void kernel_launch(void* const* d_in, const int* in_sizes, int n_in,
                              void* d_out, int out_size) {
    const int*   xk  = (const int*)  d_in[0];
    const float* emb = (const float*)d_in[1];
    const float* WQ  = (const float*)d_in[2];
    const float* WK  = (const float*)d_in[3];
    const float* WV  = (const float*)d_in[4];
    const float* WO  = (const float*)d_in[5];
    const float* W1  = (const float*)d_in[6];
    const float* b1  = (const float*)d_in[7];
    const float* W2  = (const float*)d_in[8];
    const float* b2  = (const float*)d_in[9];
    const float* g1  = (const float*)d_in[10];
    const float* be1 = (const float*)d_in[11];
    const float* g2  = (const float*)d_in[12];
    const float* be2 = (const float*)d_in[13];
    const float* Vd  = (const float*)d_in[14];
    const float* gf  = (const float*)d_in[15];
    const float* bf  = (const float*)d_in[16];
    float* outp = (float*)d_out;

    float *acc, *outb, *xa, *tmp, *qh, *kh, *vh, *attn, *ffh, *pe, *po, *ps, *part, *sums, *logits;
    cudaGetSymbolAddress((void**)&acc,   g_acc);
    cudaGetSymbolAddress((void**)&outb,  g_out);
    cudaGetSymbolAddress((void**)&xa,    g_xa);
    cudaGetSymbolAddress((void**)&tmp,   g_tmp);
    cudaGetSymbolAddress((void**)&qh,    g_qh);
    cudaGetSymbolAddress((void**)&kh,    g_kh);
    cudaGetSymbolAddress((void**)&vh,    g_vh);
    cudaGetSymbolAddress((void**)&attn,  g_attn);
    cudaGetSymbolAddress((void**)&ffh,   g_ffh);
    cudaGetSymbolAddress((void**)&pe,    g_pe);
    cudaGetSymbolAddress((void**)&po,    g_po);
    cudaGetSymbolAddress((void**)&ps,    g_ps);
    cudaGetSymbolAddress((void**)&part,  g_part);
    cudaGetSymbolAddress((void**)&sums,  g_sums);
    cudaGetSymbolAddress((void**)&logits,g_logits);

    // allow >48KB dynamic smem for the pipelined GEMMs (idempotent, capture-safe)
    static bool attr_done = false;
    if (!attr_done) {
        cudaFuncSetAttribute(qkv_tc, cudaFuncAttributeMaxDynamicSharedMemorySize, SMEM_BN64);
        cudaFuncSetAttribute(gemm_tc<64, false,false,true>,  cudaFuncAttributeMaxDynamicSharedMemorySize, SMEM_BN64);
        cudaFuncSetAttribute(gemm_tc<128, true,true,false>,  cudaFuncAttributeMaxDynamicSharedMemorySize, SMEM_BN128);
        cudaFuncSetAttribute(gemm_tc<64, false,true,true>,   cudaFuncAttributeMaxDynamicSharedMemorySize, SMEM_BN64);
        attr_done = true;
    }

    pe_kernel<<<SEQ, 128>>>(pe);
    embed_kernel<<<ROWS, 128>>>(xk, emb, pe, acc);

    const int MB = ROWS / 128;   // 128 m-blocks

    for (int l = 0; l < NL; l++) {
        const float* wq = WQ + (size_t)l * HID * HDIM;
        const float* wk = WK + (size_t)l * HID * HDIM;
        const float* wv = WV + (size_t)l * HID * HDIM;
        const float* wo = WO + (size_t)l * HDIM * HID;
        const float* w1 = W1 + (size_t)l * HID * FF;
        const float* w2 = W2 + (size_t)l * FF * HID;
        const float* bb1 = b1 + (size_t)l * FF;
        const float* bb2 = b2 + (size_t)l * HID;

        qkv_tc<<<dim3(1, MB, 3), 256, SMEM_BN64>>>(acc, wq, wk, wv, qh, kh, vh);

        attn_part<<<dim3(NH, BATCH, 2), 128>>>(qh, kh, vh, xk, po, ps);
        attn_combine<<<ROWS * NH / 256, 256>>>(po, ps, attn);

        dim3 go((HID + 63) / 64, MB);
        gemm_tc<64, false,false,true><<<go, 256, SMEM_BN64>>>(attn, wo, nullptr, acc, tmp, HID, HDIM);
        ln_kernel<false><<<ROWS/8, 256>>>(tmp, xa, g1 + l, be1 + l, nullptr);

        dim3 gf1((FF + 127) / 128, MB);
        gemm_tc<128, true,true,false><<<gf1, 256, SMEM_BN128>>>(xa, w1, bb1, nullptr, ffh, FF, HID);
        gemm_tc<64, false,true,true><<<go, 256, SMEM_BN64>>>(ffh, w2, bb2, xa, tmp, HID, FF);
        ln_kernel<true><<<ROWS/8, 256>>>(tmp, outb, g2 + l, be2 + l, acc);
    }

    seqsum1<<<dim3(BATCH, 8), 320>>>(outb, part);
    seqsum2<<<BATCH, 320>>>(part, sums);
    classify_kernel<<<dim3((NC + 255) / 256, BATCH), 256>>>(sums, Vd, logits);
    final_kernel<<<BATCH, 256>>>(logits, gf, bf, outp);
}

// round 15
// speedup vs baseline: 1.0974x; 1.0031x over previous
#include <cuda_runtime.h>
#include <math.h>

#define SEQ   512
#define BATCH 32
#define ROWS  16384        // BATCH*SEQ
#define HID   300
#define HDIM  64
#define NH    8
#define DH    8
#define NL    6
#define FF    1200
#define NC    1000

// ---------------- scratch (static device globals; no allocation) ----------------
__device__ float g_acc [ROWS*HID];
__device__ float g_out [ROWS*HID];
__device__ float g_xa  [ROWS*HID];
__device__ float g_tmp [ROWS*HID];
__device__ float g_qh  [ROWS*HDIM];
__device__ float g_kh  [ROWS*HDIM];
__device__ float g_vh  [ROWS*HDIM];
__device__ float g_attn[ROWS*HDIM];
__device__ float g_ffh [ROWS*FF];
__device__ float g_pe  [SEQ*HID];
__device__ float g_po  [2*ROWS*NH*8];   // split-K partial outputs
__device__ float g_ps  [2*ROWS*NH];     // split-K partial sums
__device__ float g_part[8*BATCH*HID];
__device__ float g_sums[BATCH*HID];
__device__ float g_logits[BATCH*NC];

// ---------------- positional encoding table ----------------
__global__ void pe_kernel(float* __restrict__ pe) {
    int s = blockIdx.x;
    for (int c = threadIdx.x; c < HID; c += blockDim.x) {
        double expo = (double)(c & ~1) / (double)HID;
        double ang  = (double)s * exp(-expo * 9.210340371976182736); // ln(10000)
        pe[s*HID + c] = (c & 1) ? (float)cos(ang) : (float)sin(ang);
    }
}

// acc = 2*emb[token] + PE   (x2 = emb+PE; acc = x2 + x1)
__global__ void embed_kernel(const int* __restrict__ tok,
                             const float* __restrict__ emb,
                             const float* __restrict__ pe,
                             float* __restrict__ accb) {
    int row = blockIdx.x;
    int s   = row & (SEQ - 1);
    long long t = tok[row];
    const float* er = emb + t * HID;
    const float* pr = pe + s * HID;
    for (int c = threadIdx.x; c < HID; c += blockDim.x) {
        accb[row*HID + c] = 2.f * er[c] + pr[c];
    }
}

// ================= tf32 tensor-core GEMM, 3-stage cp.async pipeline (R8 config) =================

__device__ __forceinline__ void mma_tf32(float d[4], const unsigned a[4],
                                         const unsigned b[2], const float c[4]) {
    asm volatile(
        "mma.sync.aligned.m16n8k8.row.col.f32.tf32.tf32.f32 "
        "{%0,%1,%2,%3}, {%4,%5,%6,%7}, {%8,%9}, {%10,%11,%12,%13};\n"
        : "=f"(d[0]), "=f"(d[1]), "=f"(d[2]), "=f"(d[3])
        : "r"(a[0]), "r"(a[1]), "r"(a[2]), "r"(a[3]),
          "r"(b[0]), "r"(b[1]),
          "f"(c[0]), "f"(c[1]), "f"(c[2]), "f"(c[3]));
}

__device__ __forceinline__ void cp16(void* smem, const void* gmem) {
    unsigned saddr = (unsigned)__cvta_generic_to_shared(smem);
    asm volatile("cp.async.cg.shared.global [%0], [%1], 16;" :: "r"(saddr), "l"(gmem));
}

#define AS_LD 20    // 128x16 A tile, m-major rows padded to 20 floats
#define NSTAGE 3

// HM: head-major scatter store for QKV outputs (N==64, col = d*8+h)
template<int BN, bool RELU, bool BIAS, bool RES, bool HM>
__device__ __forceinline__ void gemm_body(const float* __restrict__ A,
                                          const float* __restrict__ B,
                                          const float* __restrict__ bias,
                                          const float* __restrict__ res,
                                          float* __restrict__ C,
                                          int N, int K, int bm, int bn) {
    constexpr int BS_LD = BN + 8;     // %32 == 8 -> conflict-free
    constexpr int NT = BN / 16;       // n-tiles of 8 per warp
    extern __shared__ float dsm[];
    float (*As)[128][AS_LD] = (float (*)[128][AS_LD])dsm;
    float (*Bs)[16][BS_LD]  = (float (*)[16][BS_LD])(dsm + NSTAGE * 128 * AS_LD);

    const int tid  = threadIdx.x;
    const int lane = tid & 31, warp = tid >> 5;
    const int gid  = lane >> 2, tig = lane & 3;
    const int rowb = (warp & 3) * 32;          // 4 warps over M
    const int nb   = (warp >> 2) * (BN / 2);   // 2 warps over N

    float acc[2][NT][4];
#pragma unroll
    for (int mt = 0; mt < 2; mt++)
#pragma unroll
        for (int nt = 0; nt < NT; nt++)
#pragma unroll
            for (int i = 0; i < 4; i++) acc[mt][nt][i] = 0.f;

    const int S = (K + 15) / 16;

    auto issue = [&](int s) {
        int buf = s % NSTAGE;
        int k0 = s * 16;
#pragma unroll
        for (int j = 0; j < 2; j++) {
            int idx = tid + j * 256;
            int r = idx >> 2, c4 = (idx & 3) * 4;
            float* dst = &As[buf][r][c4];
            if (k0 + c4 < K) cp16(dst, A + (size_t)(bm + r) * K + k0 + c4);
            else *(float4*)dst = make_float4(0.f, 0.f, 0.f, 0.f);
        }
#pragma unroll
        for (int j = 0; j < BN / 64; j++) {
            int idx = tid + j * 256;
            int r = idx / (BN / 4);
            int c4 = (idx % (BN / 4)) * 4;
            float* dst = &Bs[buf][r][c4];
            int gr = k0 + r, gc = bn + c4;
            if (gr < K && gc < N) cp16(dst, B + (size_t)gr * N + gc);
            else *(float4*)dst = make_float4(0.f, 0.f, 0.f, 0.f);
        }
        asm volatile("cp.async.commit_group;");
    };

    issue(0);
    if (S > 1) issue(1);

    for (int s = 0; s < S; s++) {
        if (s + 1 < S) asm volatile("cp.async.wait_group 1;");
        else           asm volatile("cp.async.wait_group 0;");
        __syncthreads();
        if (s + 2 < S) issue(s + 2);

        const float (*as)[AS_LD] = As[s % NSTAGE];
        const float (*bs)[BS_LD] = Bs[s % NSTAGE];
#pragma unroll
        for (int ks = 0; ks < 2; ks++) {
            const int kk = ks * 8;
            unsigned af[2][4], bf[NT][2];
#pragma unroll
            for (int mt = 0; mt < 2; mt++) {
                int r0 = rowb + mt * 16 + gid;
                af[mt][0] = __float_as_uint(as[r0    ][kk + tig    ]);
                af[mt][1] = __float_as_uint(as[r0 + 8][kk + tig    ]);
                af[mt][2] = __float_as_uint(as[r0    ][kk + tig + 4]);
                af[mt][3] = __float_as_uint(as[r0 + 8][kk + tig + 4]);
            }
#pragma unroll
            for (int nt = 0; nt < NT; nt++) {
                int c0 = nb + nt * 8 + gid;
                bf[nt][0] = __float_as_uint(bs[kk + tig    ][c0]);
                bf[nt][1] = __float_as_uint(bs[kk + tig + 4][c0]);
            }
#pragma unroll
            for (int mt = 0; mt < 2; mt++)
#pragma unroll
                for (int nt = 0; nt < NT; nt++)
                    mma_tf32(acc[mt][nt], af[mt], bf[nt], acc[mt][nt]);
        }
    }

    // epilogue
#pragma unroll
    for (int mt = 0; mt < 2; mt++) {
        int row0 = bm + rowb + mt * 16 + gid;
#pragma unroll
        for (int nt = 0; nt < NT; nt++) {
            int col = bn + nb + nt * 8 + 2 * tig;
#pragma unroll
            for (int half = 0; half < 2; half++) {
                int row = row0 + half * 8;
                float v0 = acc[mt][nt][half * 2 + 0];
                float v1 = acc[mt][nt][half * 2 + 1];
                if (HM) {
                    C[(((size_t)(col & 7)) * ROWS + row) * 8 + (col >> 3)] = v0;
                    C[(((size_t)((col + 1) & 7)) * ROWS + row) * 8 + ((col + 1) >> 3)] = v1;
                } else {
                    if (col < N) {
                        if (BIAS) v0 += bias[col];
                        if (RES)  v0 += res[(size_t)row * N + col];
                        if (RELU) v0 = fmaxf(v0, 0.f);
                        C[(size_t)row * N + col] = v0;
                    }
                    if (col + 1 < N) {
                        if (BIAS) v1 += bias[col + 1];
                        if (RES)  v1 += res[(size_t)row * N + col + 1];
                        if (RELU) v1 = fmaxf(v1, 0.f);
                        C[(size_t)row * N + col + 1] = v1;
                    }
                }
            }
        }
    }
}

template<int BN, bool RELU, bool BIAS, bool RES>
__global__ void __launch_bounds__(256) gemm_tc(const float* __restrict__ A,
                                               const float* __restrict__ B,
                                               const float* __restrict__ bias,
                                               const float* __restrict__ res,
                                               float* __restrict__ C,
                                               int N, int K) {
    gemm_body<BN, RELU, BIAS, RES, false>(A, B, bias, res, C, N, K,
                                          blockIdx.y * 128, blockIdx.x * BN);
}

// fused QKV with head-major output: grid (1, M/128, 3)
__global__ void __launch_bounds__(256) qkv_tc(const float* __restrict__ A,
                                              const float* __restrict__ WQa,
                                              const float* __restrict__ WKa,
                                              const float* __restrict__ WVa,
                                              float* __restrict__ Qh,
                                              float* __restrict__ Kh,
                                              float* __restrict__ Vh) {
    const float* B = (blockIdx.z == 0) ? WQa : (blockIdx.z == 1) ? WKa : WVa;
    float* C = (blockIdx.z == 0) ? Qh : (blockIdx.z == 1) ? Kh : Vh;
    gemm_body<64, false, false, false, true>(A, B, nullptr, nullptr, C, HDIM, HID,
                                             blockIdx.y * 128, 0);
}

// smem byte sizes for the pipeline
#define SMEM_BN64  ((NSTAGE*128*AS_LD + NSTAGE*16*(64+8)) * 4)
#define SMEM_BN128 ((NSTAGE*128*AS_LD + NSTAGE*16*(128+8)) * 4)

__device__ __forceinline__ float ex2(float x) {
    float r;
    asm("ex2.approx.f32 %0, %1;" : "=f"(r) : "f"(x));
    return r;
}

// ---------------- attention part 1: split-K, 4 queries/thread ----------------
// grid (NH, BATCH, 2): z = key-half; 128 threads; thread handles queries tid+{0,128,256,384}
// writes partial (ssum, o[8]) per (query, head, half)
__global__ void __launch_bounds__(128) attn_part(const float* __restrict__ Qh,
                                                 const float* __restrict__ Kh,
                                                 const float* __restrict__ Vh,
                                                 const int* __restrict__ tok,
                                                 float* __restrict__ po,
                                                 float* __restrict__ ps) {
    const int h = blockIdx.x;
    const int b = blockIdx.y;
    const int z = blockIdx.z;              // key half
    const int base = b * SEQ;
    const int koff = z * 256;
    __shared__ float Ks[256][8];
    __shared__ float Vs[256][8];
    __shared__ float mmul[256];
    const int tid = threadIdx.x;   // 128

    const float4* kp = (const float4*)(Kh + ((size_t)h * ROWS + base + koff) * 8);
    const float4* vp = (const float4*)(Vh + ((size_t)h * ROWS + base + koff) * 8);
    float4* Ks4 = (float4*)Ks;
    float4* Vs4 = (float4*)Vs;
#pragma unroll
    for (int i = 0; i < 4; i++) {
        int idx = tid + i * 128;       // 512 float4 per tensor
        Ks4[idx] = kp[idx];
        Vs4[idx] = vp[idx];
    }
#pragma unroll
    for (int i = 0; i < 2; i++) {
        int idx = tid + i * 128;
        mmul[idx] = (tok[base + koff + idx] == 0) ? 0.f : 1.f;
    }
    __syncthreads();

    // fold 1/sqrt(300)*log2(e) into q; use ex2.approx
    const float scale = 0.05773502691896258f * 1.4426950408889634f;
    float q[4][8];
#pragma unroll
    for (int j = 0; j < 4; j++) {
        const float* qp = Qh + ((size_t)h * ROWS + base + tid + j * 128) * 8;
        float4 x0 = *(const float4*)qp;
        float4 x1 = *(const float4*)(qp + 4);
        q[j][0]=x0.x*scale; q[j][1]=x0.y*scale; q[j][2]=x0.z*scale; q[j][3]=x0.w*scale;
        q[j][4]=x1.x*scale; q[j][5]=x1.y*scale; q[j][6]=x1.z*scale; q[j][7]=x1.w*scale;
    }

    float ssum[4], o[4][8];
#pragma unroll
    for (int j = 0; j < 4; j++) {
        ssum[j] = 0.f;
#pragma unroll
        for (int d = 0; d < 8; d++) o[j][d] = 0.f;
    }

#pragma unroll 2
    for (int k = 0; k < 256; k++) {
        float4 k0 = *(const float4*)&Ks[k][0];
        float4 k1 = *(const float4*)&Ks[k][4];
        float m = mmul[k];
        float4 v0 = *(const float4*)&Vs[k][0];
        float4 v1 = *(const float4*)&Vs[k][4];
#pragma unroll
        for (int j = 0; j < 4; j++) {
            float d = q[j][0]*k0.x + q[j][1]*k0.y + q[j][2]*k0.z + q[j][3]*k0.w
                    + q[j][4]*k1.x + q[j][5]*k1.y + q[j][6]*k1.z + q[j][7]*k1.w;
            float p = ex2(d) * m;
            ssum[j] += p;
            o[j][0] += p * v0.x; o[j][1] += p * v0.y; o[j][2] += p * v0.z; o[j][3] += p * v0.w;
            o[j][4] += p * v1.x; o[j][5] += p * v1.y; o[j][6] += p * v1.z; o[j][7] += p * v1.w;
        }
    }

#pragma unroll
    for (int j = 0; j < 4; j++) {
        size_t grow = (size_t)base + tid + j * 128;       // global row
        size_t idx = ((size_t)z * ROWS + grow) * NH + h;  // (half, row, head)
        ps[idx] = ssum[j];
        float* op = po + idx * 8;
        *(float4*)op       = make_float4(o[j][0], o[j][1], o[j][2], o[j][3]);
        *(float4*)(op + 4) = make_float4(o[j][4], o[j][5], o[j][6], o[j][7]);
    }
}

// ---------------- attention part 2: combine halves, normalize ----------------
// one thread per (row, head); t = row*NH + h -> coalesced reads and writes
__global__ void __launch_bounds__(256) attn_combine(const float* __restrict__ po,
                                                    const float* __restrict__ ps,
                                                    float* __restrict__ O) {
    const int t = blockIdx.x * 256 + threadIdx.x;   // ROWS*NH total
    const size_t i0 = (size_t)t;                    // half 0
    const size_t i1 = (size_t)ROWS * NH + t;        // half 1
    float inv = 1.f / (ps[i0] + ps[i1]);
    const float4* p0 = (const float4*)(po + i0 * 8);
    const float4* p1 = (const float4*)(po + i1 * 8);
    float4 a0 = p0[0], a1 = p0[1];
    float4 b0 = p1[0], b1 = p1[1];
    float4 r0 = make_float4((a0.x+b0.x)*inv, (a0.y+b0.y)*inv, (a0.z+b0.z)*inv, (a0.w+b0.w)*inv);
    float4 r1 = make_float4((a1.x+b1.x)*inv, (a1.y+b1.y)*inv, (a1.z+b1.z)*inv, (a1.w+b1.w)*inv);
    // O[row][h*8 + d]; t = row*NH + h  -> O + t*8 is exactly row*64 + h*8
    float4* op = (float4*)(O + (size_t)t * 8);
    op[0] = r0;
    op[1] = r1;
}

// ---------------- LayerNorm: warp per row, shuffle reductions ----------------
template<bool ACC>
__global__ void __launch_bounds__(256) ln_kernel(const float* __restrict__ in,
                                                 float* __restrict__ outp,
                                                 const float* __restrict__ g,
                                                 const float* __restrict__ bt,
                                                 float* __restrict__ accb) {
    const int warp = threadIdx.x >> 5, lane = threadIdx.x & 31;
    const int row = blockIdx.x * 8 + warp;
    const float* x = in + (size_t)row * HID;

    float v[10];
    float s = 0.f;
#pragma unroll
    for (int i = 0; i < 10; i++) {
        int c = lane + i * 32;
        v[i] = (c < HID) ? x[c] : 0.f;
        s += v[i];
    }
#pragma unroll
    for (int o = 16; o; o >>= 1) s += __shfl_xor_sync(0xffffffffu, s, o);
    float mu = s / HID;

    float sq = 0.f;
#pragma unroll
    for (int i = 0; i < 10; i++) {
        int c = lane + i * 32;
        if (c < HID) { float d = v[i] - mu; sq += d * d; }
    }
#pragma unroll
    for (int o = 16; o; o >>= 1) sq += __shfl_xor_sync(0xffffffffu, sq, o);
    float inv = rsqrtf(sq / (HID - 1) + 1e-8f);

    float gg = g[0], bb = bt[0];
#pragma unroll
    for (int i = 0; i < 10; i++) {
        int c = lane + i * 32;
        if (c < HID) {
            float y = gg * (v[i] - mu) * inv + bb;
            outp[(size_t)row * HID + c] = y;
            if (ACC) accb[(size_t)row * HID + c] += y;
        }
    }
}

// ---------------- sum over sequence, two-stage (deterministic) ----------------
__global__ void seqsum1(const float* __restrict__ in, float* __restrict__ part) {
    int b = blockIdx.x, ch = blockIdx.y, c = threadIdx.x;
    if (c < HID) {
        float a = 0.f;
        const float* p = in + ((size_t)b * SEQ + ch * 64) * HID + c;
        for (int s = 0; s < 64; s++) a += p[(size_t)s * HID];
        part[((size_t)ch * BATCH + b) * HID + c] = a;
    }
}
__global__ void seqsum2(const float* __restrict__ part, float* __restrict__ sums) {
    int b = blockIdx.x, c = threadIdx.x;
    if (c < HID) {
        float a = 0.f;
#pragma unroll
        for (int ch = 0; ch < 8; ch++) a += part[((size_t)ch * BATCH + b) * HID + c];
        sums[b * HID + c] = a;
    }
}

// ---------------- classifier: (B,HID) @ (HID,NC) ----------------
__global__ void classify_kernel(const float* __restrict__ sums, const float* __restrict__ Vd,
                                float* __restrict__ logits) {
    int b = blockIdx.y;
    int c = blockIdx.x * 256 + threadIdx.x;
    __shared__ float srow[HID];
    for (int i = threadIdx.x; i < HID; i += 256) srow[i] = sums[b * HID + i];
    __syncthreads();
    if (c < NC) {
        float a = 0.f;
        for (int k = 0; k < HID; k++) a += srow[k] * Vd[(size_t)k * NC + c];
        logits[b * NC + c] = a;
    }
}

// ---------------- final LN (ddof=1) + softmax over NC ----------------
__global__ void final_kernel(const float* __restrict__ logits,
                             const float* __restrict__ gf, const float* __restrict__ bf,
                             float* __restrict__ outp) {
    const int b = blockIdx.x;
    const int t = threadIdx.x;   // 256
    __shared__ float buf[NC];
    __shared__ float red[256];
    const float* x = logits + (size_t)b * NC;

    float s = 0.f;
    for (int c = t; c < NC; c += 256) { float v = x[c]; buf[c] = v; s += v; }
    red[t] = s; __syncthreads();
    for (int st = 128; st > 0; st >>= 1) { if (t < st) red[t] += red[t + st]; __syncthreads(); }
    float mu = red[0] / NC;
    __syncthreads();

    float sq = 0.f;
    for (int c = t; c < NC; c += 256) { float d = buf[c] - mu; sq += d * d; }
    red[t] = sq; __syncthreads();
    for (int st = 128; st > 0; st >>= 1) { if (t < st) red[t] += red[t + st]; __syncthreads(); }
    float inv = rsqrtf(red[0] / (NC - 1) + 1e-8f);
    float gg = gf[0], bb = bf[0];
    __syncthreads();

    for (int c = t; c < NC; c += 256) buf[c] = gg * (buf[c] - mu) * inv + bb;
    __syncthreads();

    float mx = -1e30f;
    for (int c = t; c < NC; c += 256) mx = fmaxf(mx, buf[c]);
    red[t] = mx; __syncthreads();
    for (int st = 128; st > 0; st >>= 1) { if (t < st) red[t] = fmaxf(red[t], red[t + st]); __syncthreads(); }
    float rmax = red[0];
    __syncthreads();

    float es = 0.f;
    for (int c = t; c < NC; c += 256) es += __expf(buf[c] - rmax);
    red[t] = es; __syncthreads();
    for (int st = 128; st > 0; st >>= 1) { if (t < st) red[t] += red[t + st]; __syncthreads(); }
    float invs = 1.f / red[0];
    __syncthreads();

    for (int c = t; c < NC; c += 256) outp[(size_t)b * NC + c] = __expf(buf[c] - rmax) * invs;
}

// ---------------- launch ----------------
extern "C" void kernel_launch(void* const* d_in, const int* in_sizes, int n_in,
                              void* d_out, int out_size) {
    const int*   xk  = (const int*)  d_in[0];
    const float* emb = (const float*)d_in[1];
    const float* WQ  = (const float*)d_in[2];
    const float* WK  = (const float*)d_in[3];
    const float* WV  = (const float*)d_in[4];
    const float* WO  = (const float*)d_in[5];
    const float* W1  = (const float*)d_in[6];
    const float* b1  = (const float*)d_in[7];
    const float* W2  = (const float*)d_in[8];
    const float* b2  = (const float*)d_in[9];
    const float* g1  = (const float*)d_in[10];
    const float* be1 = (const float*)d_in[11];
    const float* g2  = (const float*)d_in[12];
    const float* be2 = (const float*)d_in[13];
    const float* Vd  = (const float*)d_in[14];
    const float* gf  = (const float*)d_in[15];
    const float* bf  = (const float*)d_in[16];
    float* outp = (float*)d_out;

    float *acc, *outb, *xa, *tmp, *qh, *kh, *vh, *attn, *ffh, *pe, *po, *ps, *part, *sums, *logits;
    cudaGetSymbolAddress((void**)&acc,   g_acc);
    cudaGetSymbolAddress((void**)&outb,  g_out);
    cudaGetSymbolAddress((void**)&xa,    g_xa);
    cudaGetSymbolAddress((void**)&tmp,   g_tmp);
    cudaGetSymbolAddress((void**)&qh,    g_qh);
    cudaGetSymbolAddress((void**)&kh,    g_kh);
    cudaGetSymbolAddress((void**)&vh,    g_vh);
    cudaGetSymbolAddress((void**)&attn,  g_attn);
    cudaGetSymbolAddress((void**)&ffh,   g_ffh);
    cudaGetSymbolAddress((void**)&pe,    g_pe);
    cudaGetSymbolAddress((void**)&po,    g_po);
    cudaGetSymbolAddress((void**)&ps,    g_ps);
    cudaGetSymbolAddress((void**)&part,  g_part);
    cudaGetSymbolAddress((void**)&sums,  g_sums);
    cudaGetSymbolAddress((void**)&logits,g_logits);

    // allow >48KB dynamic smem for the pipelined GEMMs (idempotent, capture-safe)
    static bool attr_done = false;
    if (!attr_done) {
        cudaFuncSetAttribute(qkv_tc, cudaFuncAttributeMaxDynamicSharedMemorySize, SMEM_BN64);
        cudaFuncSetAttribute(gemm_tc<64, false,false,true>,  cudaFuncAttributeMaxDynamicSharedMemorySize, SMEM_BN64);
        cudaFuncSetAttribute(gemm_tc<128, true,true,false>,  cudaFuncAttributeMaxDynamicSharedMemorySize, SMEM_BN128);
        cudaFuncSetAttribute(gemm_tc<64, false,true,true>,   cudaFuncAttributeMaxDynamicSharedMemorySize, SMEM_BN64);
        attr_done = true;
    }

    pe_kernel<<<SEQ, 128>>>(pe);
    embed_kernel<<<ROWS, 128>>>(xk, emb, pe, acc);

    const int MB = ROWS / 128;   // 128 m-blocks

    for (int l = 0; l < NL; l++) {
        const float* wq = WQ + (size_t)l * HID * HDIM;
        const float* wk = WK + (size_t)l * HID * HDIM;
        const float* wv = WV + (size_t)l * HID * HDIM;
        const float* wo = WO + (size_t)l * HDIM * HID;
        const float* w1 = W1 + (size_t)l * HID * FF;
        const float* w2 = W2 + (size_t)l * FF * HID;
        const float* bb1 = b1 + (size_t)l * FF;
        const float* bb2 = b2 + (size_t)l * HID;

        qkv_tc<<<dim3(1, MB, 3), 256, SMEM_BN64>>>(acc, wq, wk, wv, qh, kh, vh);

        attn_part<<<dim3(NH, BATCH, 2), 128>>>(qh, kh, vh, xk, po, ps);
        attn_combine<<<ROWS * NH / 256, 256>>>(po, ps, attn);

        dim3 go((HID + 63) / 64, MB);
        gemm_tc<64, false,false,true><<<go, 256, SMEM_BN64>>>(attn, wo, nullptr, acc, tmp, HID, HDIM);
        ln_kernel<false><<<ROWS/8, 256>>>(tmp, xa, g1 + l, be1 + l, nullptr);

        dim3 gf1((FF + 127) / 128, MB);
        gemm_tc<128, true,true,false><<<gf1, 256, SMEM_BN128>>>(xa, w1, bb1, nullptr, ffh, FF, HID);
        gemm_tc<64, false,true,true><<<go, 256, SMEM_BN64>>>(ffh, w2, bb2, xa, tmp, HID, FF);
        ln_kernel<true><<<ROWS/8, 256>>>(tmp, outb, g2 + l, be2 + l, acc);
    }

    seqsum1<<<dim3(BATCH, 8), 320>>>(outb, part);
    seqsum2<<<BATCH, 320>>>(part, sums);
    classify_kernel<<<dim3((NC + 255) / 256, BATCH), 256>>>(sums, Vd, logits);
    final_kernel<<<BATCH, 256>>>(logits, gf, bf, outp);
}